// round 2
// baseline (speedup 1.0000x reference)
#include <cuda_runtime.h>

// BSplineTransformation: x (16,3,1024,1024) f32, control_points (1,2,35,35) f32
// out = concat(transformed (16,3,1024,1024), deformation_field (2,1024,1024))

#define HH 1024
#define WW 1024
#define NPIX (HH*WW)
#define NB 16
#define NC 3
#define CP 35
#define CP2 (CP*CP)

__global__ __launch_bounds__(256) void bspline_kernel(
    const float* __restrict__ x,
    const float* __restrict__ cp,
    float* __restrict__ out)
{
    __shared__ float scp[2*CP2];
    for (int t = threadIdx.x; t < 2*CP2; t += 256) scp[t] = cp[t];
    __syncthreads();

    const int p = blockIdx.x * 256 + threadIdx.x;   // pixel index
    const int i = p >> 10;
    const int j = p & 1023;

    // normalized grid coords (linspace(-1,1,1024))
    const float gy = fmaf((float)i, 2.0f / 1023.0f, -1.0f);
    const float gx = fmaf((float)j, 2.0f / 1023.0f, -1.0f);

    // ---- deformation field: grid_sample(control_points, border, align_corners) ----
    // cp_x = (gx+1)*(CP-1)/2 ; then grid_sample maps via ix=(v+1)*0.5*(CP-1)
    const float cx = (gx + 1.0f) * 17.0f;
    const float cy = (gy + 1.0f) * 17.0f;
    float icx = fminf(fmaxf((cx + 1.0f) * 17.0f, 0.0f), 34.0f);
    float icy = fminf(fmaxf((cy + 1.0f) * 17.0f, 0.0f), 34.0f);
    const float fcx = floorf(icx);
    const float fcy = floorf(icy);
    const int cx0 = (int)fcx;
    const int cy0 = (int)fcy;
    const int cx1 = min(cx0 + 1, CP - 1);
    const int cy1 = min(cy0 + 1, CP - 1);
    const float wx = icx - fcx;
    const float wy = icy - fcy;

    const int o00 = cy0 * CP + cx0;
    const int o01 = cy0 * CP + cx1;
    const int o10 = cy1 * CP + cx0;
    const int o11 = cy1 * CP + cx1;

    // channel 0 (added to gy), channel 1 (added to gx)
    const float t0  = scp[o00]        * (1.0f - wx) + scp[o01]        * wx;
    const float b0  = scp[o10]        * (1.0f - wx) + scp[o11]        * wx;
    const float d0  = t0 * (1.0f - wy) + b0 * wy;
    const float t1  = scp[CP2 + o00]  * (1.0f - wx) + scp[CP2 + o01]  * wx;
    const float b1  = scp[CP2 + o10]  * (1.0f - wx) + scp[CP2 + o11]  * wx;
    const float d1  = t1 * (1.0f - wy) + b1 * wy;

    // write deformation field once (batch-slice 0 only)
    if (blockIdx.y == 0) {
        float* def = out + (long long)NB * NC * NPIX;
        def[p]        = d0;
        def[NPIX + p] = d1;
    }

    // ---- main sample: grid_sample(x[b], samp) with samp = (gx+d1, gy+d0) ----
    const float sxn = gx + d1;
    const float syn = gy + d0;
    float sx = fminf(fmaxf((sxn + 1.0f) * 0.5f * 1023.0f, 0.0f), 1023.0f);
    float sy = fminf(fmaxf((syn + 1.0f) * 0.5f * 1023.0f, 0.0f), 1023.0f);
    const float fsx = floorf(sx);
    const float fsy = floorf(sy);
    const int ix0 = (int)fsx;
    const int iy0 = (int)fsy;
    const int ix1 = min(ix0 + 1, WW - 1);
    const int iy1 = min(iy0 + 1, HH - 1);
    const float ax = sx - fsx;
    const float ay = sy - fsy;

    const int q00 = (iy0 << 10) + ix0;
    const int q01 = (iy0 << 10) + ix1;
    const int q10 = (iy1 << 10) + ix0;
    const int q11 = (iy1 << 10) + ix1;

    const long long b = blockIdx.y;
    const float* imgb = x   + ((long long)(b * NC) << 20);
    float*       outb = out + ((long long)(b * NC) << 20) + p;

    #pragma unroll
    for (int c = 0; c < NC; c++) {
        const float* im = imgb + ((long long)c << 20);
        const float v00 = __ldg(im + q00);
        const float v01 = __ldg(im + q01);
        const float v10 = __ldg(im + q10);
        const float v11 = __ldg(im + q11);
        const float top = v00 * (1.0f - ax) + v01 * ax;
        const float bot = v10 * (1.0f - ax) + v11 * ax;
        outb[(long long)c << 20] = top * (1.0f - ay) + bot * ay;
    }
}

extern "C" void kernel_launch(void* const* d_in, const int* in_sizes, int n_in,
                              void* d_out, int out_size)
{
    const float* x  = (const float*)d_in[0];
    const float* cp = (const float*)d_in[1];
    float* out = (float*)d_out;

    dim3 grid(NPIX / 256, NB);
    bspline_kernel<<<grid, 256>>>(x, cp, out);
}

// round 3
// speedup vs baseline: 1.4712x; 1.4712x over previous
#include <cuda_runtime.h>

// BSplineTransformation: x (16,3,1024,1024) f32, control_points (1,2,35,35) f32
// out = concat(transformed (16,3,1024,1024), deformation_field (2,1024,1024))

#define HH 1024
#define WW 1024
#define NPIX (HH*WW)
#define NB 16
#define NC 3
#define CP 35
#define CP2 (CP*CP)
#define BATCHES_PER_BLOCK 4

__global__ __launch_bounds__(256) void bspline_kernel(
    const float* __restrict__ x,
    const float* __restrict__ cp,
    float* __restrict__ out)
{
    __shared__ float scp[2*CP2];
    for (int t = threadIdx.x; t < 2*CP2; t += 256) scp[t] = cp[t];
    __syncthreads();

    const int p = blockIdx.x * 256 + threadIdx.x;   // pixel index
    const int i = p >> 10;
    const int j = p & 1023;

    // normalized grid coords (linspace(-1,1,1024))
    const float gy = fmaf((float)i, 2.0f / 1023.0f, -1.0f);
    const float gx = fmaf((float)j, 2.0f / 1023.0f, -1.0f);

    // ---- deformation field: grid_sample(control_points, border, align_corners) ----
    const float cx = (gx + 1.0f) * 17.0f;
    const float cy = (gy + 1.0f) * 17.0f;
    float icx = fminf(fmaxf((cx + 1.0f) * 17.0f, 0.0f), 34.0f);
    float icy = fminf(fmaxf((cy + 1.0f) * 17.0f, 0.0f), 34.0f);
    const float fcx = floorf(icx);
    const float fcy = floorf(icy);
    const int cx0 = (int)fcx;
    const int cy0 = (int)fcy;
    const int cx1 = min(cx0 + 1, CP - 1);
    const int cy1 = min(cy0 + 1, CP - 1);
    const float wx = icx - fcx;
    const float wy = icy - fcy;

    const int o00 = cy0 * CP + cx0;
    const int o01 = cy0 * CP + cx1;
    const int o10 = cy1 * CP + cx0;
    const int o11 = cy1 * CP + cx1;

    // channel 0 (added to gy), channel 1 (added to gx)
    const float t0 = fmaf(wx, scp[o01] - scp[o00], scp[o00]);
    const float b0 = fmaf(wx, scp[o11] - scp[o10], scp[o10]);
    const float d0 = fmaf(wy, b0 - t0, t0);
    const float t1 = fmaf(wx, scp[CP2+o01] - scp[CP2+o00], scp[CP2+o00]);
    const float b1 = fmaf(wx, scp[CP2+o11] - scp[CP2+o10], scp[CP2+o10]);
    const float d1 = fmaf(wy, b1 - t1, t1);

    // write deformation field once
    if (blockIdx.y == 0) {
        float* def = out + (long long)NB * NC * NPIX;
        def[p]        = d0;
        def[NPIX + p] = d1;
    }

    // ---- main sample: grid_sample(x[b], samp) with samp = (gx+d1, gy+d0) ----
    float sx = fminf(fmaxf((gx + d1 + 1.0f) * 511.5f, 0.0f), 1023.0f);
    float sy = fminf(fmaxf((gy + d0 + 1.0f) * 511.5f, 0.0f), 1023.0f);
    const float fsx = floorf(sx);
    const float fsy = floorf(sy);
    const int ix0 = (int)fsx;
    const int iy0 = (int)fsy;
    const int ix1 = min(ix0 + 1, WW - 1);
    const int iy1 = min(iy0 + 1, HH - 1);
    const float ax = sx - fsx;
    const float ay = sy - fsy;

    const int q00 = (iy0 << 10) + ix0;
    const int q01 = (iy0 << 10) + ix1;
    const int q10 = (iy1 << 10) + ix0;
    const int q11 = (iy1 << 10) + ix1;

    // each thread handles BATCHES_PER_BLOCK batches x 3 channels with one setup
    const int bstart = blockIdx.y * BATCHES_PER_BLOCK;

    #pragma unroll
    for (int bb = 0; bb < BATCHES_PER_BLOCK; bb++) {
        const int img0 = (bstart + bb) * NC;            // image index of channel 0
        #pragma unroll
        for (int c = 0; c < NC; c++) {
            const float* im = x + ((long long)(img0 + c) << 20);
            const float v00 = __ldg(im + q00);
            const float v01 = __ldg(im + q01);
            const float v10 = __ldg(im + q10);
            const float v11 = __ldg(im + q11);
            const float top = fmaf(ax, v01 - v00, v00);
            const float bot = fmaf(ax, v11 - v10, v10);
            out[((long long)(img0 + c) << 20) + p] = fmaf(ay, bot - top, top);
        }
    }
}

extern "C" void kernel_launch(void* const* d_in, const int* in_sizes, int n_in,
                              void* d_out, int out_size)
{
    const float* x  = (const float*)d_in[0];
    const float* cp = (const float*)d_in[1];
    float* out = (float*)d_out;

    dim3 grid(NPIX / 256, NB / BATCHES_PER_BLOCK);
    bspline_kernel<<<grid, 256>>>(x, cp, out);
}